// round 17
// baseline (speedup 1.0000x reference)
#include <cuda_runtime.h>
#include <cuda_bf16.h>
#include <cstdint>

#define NN 50000
#define EE 800000
#define NCLS 40
#define SLOT 128     // padded CSR slots per node; P(deg>128) ~ 1e-80
#define LOG2E 1.4426950408889634f

#define NTILES 391          // ceil(NN/128)
#define NCHUNK 4
// chunk tile counts: 98,98,98,97
#define CH_TILES(i) ((i) < 3 ? 98 : 97)
#define CH_TILE0(i) ((i) * 98)

#define A_STRIDE 36
#define B_STRIDE 136
#define A2_STRIDE 68
#define B2_STRIDE 44

// ---------------- device scratch (static, allocation-free) ----------------
__device__ __align__(16) float g_H1[NN * 128];    // layer1 features (fp32)
__device__ __align__(16) float g_out1[NN * 128];  // layer1 output after ELU
__device__ __align__(16) float g_H2[NN * NCLS];   // layer2 features
__device__ __align__(16) float g_asrc1[NN * 8];   // logits pre-scaled by log2(e)
__device__ __align__(16) float g_adst1[NN * 8];
__device__ float g_asrc2[NN];
__device__ float g_adst2[NN];
__device__ int g_deg[NN];          // zeroed by agg2 each replay (starts zero)
__device__ int g_csr[NN * SLOT];   // padded CSR
// precomputed bf16 hi/lo weight tiles in smem-ready layout
__device__ __align__(16) uint32_t g_W1h[2][32 * B_STRIDE];
__device__ __align__(16) uint32_t g_W1l[2][32 * B_STRIDE];
__device__ __align__(16) uint32_t g_W2h[64 * B2_STRIDE];
__device__ __align__(16) uint32_t g_W2l[64 * B2_STRIDE];

__device__ __forceinline__ float lrelu(float x) { return fmaxf(x, 0.2f * x); }
__device__ __forceinline__ float ex2(float x) {
    float r;
    asm("ex2.approx.ftz.f32 %0, %1;" : "=f"(r) : "f"(x));
    return r;
}

// ---------------- weight prep: split W1/W2 into bf16 hi/lo tile layouts ------
__global__ void prep_kernel(const float* __restrict__ W1, const float* __restrict__ W2) {
    int i = blockIdx.x * blockDim.x + threadIdx.x;
    if (i < 16384) {                       // W1: 2 chunks x 64 k x 128 j
        int kc = i >> 13, r = i & 8191;
        int k = r >> 7, j = r & 127;
        float w = W1[(kc * 64 + k) * 128 + j];
        __nv_bfloat16 hi = __float2bfloat16(w);
        __nv_bfloat16 lo = __float2bfloat16(w - __bfloat162float(hi));
        int word = (k >> 1) * B_STRIDE + j;
        ((__nv_bfloat16*)(g_W1h[kc] + word))[k & 1] = hi;
        ((__nv_bfloat16*)(g_W1l[kc] + word))[k & 1] = lo;
    } else if (i < 16384 + 5120) {         // W2: 128 k x 40 j
        int r = i - 16384;
        int k = r / NCLS, j = r % NCLS;
        float w = W2[r];
        __nv_bfloat16 hi = __float2bfloat16(w);
        __nv_bfloat16 lo = __float2bfloat16(w - __bfloat162float(hi));
        int word = (k >> 1) * B2_STRIDE + j;
        ((__nv_bfloat16*)(g_W2h + word))[k & 1] = hi;
        ((__nv_bfloat16*)(g_W2l + word))[k & 1] = lo;
    }
}

// ---------------- CSR build: single pass into padded slots ----------------
__global__ void fill_kernel(const int* __restrict__ ei) {
    int q = blockIdx.x * blockDim.x + threadIdx.x;
    if (q < EE / 4) {
        int4 s4 = __ldg((const int4*)ei + q);
        int4 d4 = __ldg((const int4*)(ei + EE) + q);
        int p0 = atomicAdd(&g_deg[d4.x], 1);
        int p1 = atomicAdd(&g_deg[d4.y], 1);
        int p2 = atomicAdd(&g_deg[d4.z], 1);
        int p3 = atomicAdd(&g_deg[d4.w], 1);
        g_csr[(d4.x << 7) + p0] = s4.x;
        g_csr[(d4.y << 7) + p1] = s4.y;
        g_csr[(d4.z << 7) + p2] = s4.z;
        g_csr[(d4.w << 7) + p3] = s4.w;
    }
}

// ---------------- shared MMA helpers ----------------
__device__ __forceinline__ void mma_bf16(float* c, const uint32_t* a, uint32_t b0, uint32_t b1) {
    asm volatile(
        "mma.sync.aligned.m16n8k16.row.col.f32.bf16.bf16.f32 "
        "{%0,%1,%2,%3}, {%4,%5,%6,%7}, {%8,%9}, {%0,%1,%2,%3};"
        : "+f"(c[0]), "+f"(c[1]), "+f"(c[2]), "+f"(c[3])
        : "r"(a[0]), "r"(a[1]), "r"(a[2]), "r"(a[3]), "r"(b0), "r"(b1));
}

__device__ __forceinline__ uint32_t pack_bf2(float a, float b) {
    __nv_bfloat162 h = __floats2bfloat162_rn(a, b);
    return *(uint32_t*)&h;
}

// ---------------- GEMM1 via mma.sync bf16 (3-term hi/lo split) + fused attn1 ----
#define SM_AHI 0
#define SM_ALO (128 * A_STRIDE)
#define SM_BHI (2 * 128 * A_STRIDE)
#define SM_BLO (2 * 128 * A_STRIDE + 32 * B_STRIDE)
#define SM_WORDS (2 * 128 * A_STRIDE + 2 * 32 * B_STRIDE)

__global__ void __launch_bounds__(256, 2)
gemm1_mma_kernel(const float* __restrict__ x,
                 const float* __restrict__ as, const float* __restrict__ ad) {
    extern __shared__ uint32_t sm[];
    uint32_t* Ahi = sm + SM_AHI;
    uint32_t* Alo = sm + SM_ALO;
    uint32_t* Bhi = sm + SM_BHI;
    uint32_t* Blo = sm + SM_BLO;

    int t = threadIdx.x, wid = t >> 5, lane = t & 31;
    int wr = wid & 3, wc = wid >> 2;
    int nbase = blockIdx.x * 128;

    float c[2][8][4];
#pragma unroll
    for (int rs = 0; rs < 2; rs++)
#pragma unroll
        for (int nf = 0; nf < 8; nf++)
#pragma unroll
            for (int q = 0; q < 4; q++) c[rs][nf][q] = 0.f;

    for (int kc = 0; kc < 2; kc++) {
        if (kc) __syncthreads();
#pragma unroll
        for (int i = 0; i < 8; i++) {
            int idx = t + 256 * i;
            int r = idx >> 4, c4 = idx & 15;
            int node = nbase + r;
            float4 v = make_float4(0.f, 0.f, 0.f, 0.f);
            if (node < NN) v = ((const float4*)x)[node * 32 + kc * 16 + c4];
            uint32_t h0 = pack_bf2(v.x, v.y), h1 = pack_bf2(v.z, v.w);
            __nv_bfloat162 hh0 = *(__nv_bfloat162*)&h0;
            __nv_bfloat162 hh1 = *(__nv_bfloat162*)&h1;
            uint32_t l0 = pack_bf2(v.x - __bfloat162float(hh0.x), v.y - __bfloat162float(hh0.y));
            uint32_t l1 = pack_bf2(v.z - __bfloat162float(hh1.x), v.w - __bfloat162float(hh1.y));
            int w = r * A_STRIDE + c4 * 2;
            Ahi[w] = h0; Ahi[w + 1] = h1;
            Alo[w] = l0; Alo[w + 1] = l1;
        }
        // copy precomputed W1 tiles (int4)
#pragma unroll
        for (int i = 0; i < 5; i++) {
            int idx = t + 256 * i;           // 1088 int4 per buffer
            if (idx < 1088) {
                ((int4*)Bhi)[idx] = __ldg((const int4*)g_W1h[kc] + idx);
                ((int4*)Blo)[idx] = __ldg((const int4*)g_W1l[kc] + idx);
            }
        }
        __syncthreads();

#pragma unroll
        for (int kk = 0; kk < 4; kk++) {
            uint32_t ah[2][4], al[2][4];
#pragma unroll
            for (int rs = 0; rs < 2; rs++) {
                int row = wr * 32 + rs * 16 + (lane >> 2);
                int base = row * A_STRIDE + kk * 8 + (lane & 3);
                ah[rs][0] = Ahi[base];
                ah[rs][1] = Ahi[base + 8 * A_STRIDE];
                ah[rs][2] = Ahi[base + 4];
                ah[rs][3] = Ahi[base + 8 * A_STRIDE + 4];
                al[rs][0] = Alo[base];
                al[rs][1] = Alo[base + 8 * A_STRIDE];
                al[rs][2] = Alo[base + 4];
                al[rs][3] = Alo[base + 8 * A_STRIDE + 4];
            }
#pragma unroll
            for (int nf = 0; nf < 8; nf++) {
                int j = wc * 64 + nf * 8 + (lane >> 2);
                int bw = (kk * 8 + (lane & 3)) * B_STRIDE + j;
                uint32_t bh0 = Bhi[bw], bh1 = Bhi[bw + 4 * B_STRIDE];
                uint32_t bl0 = Blo[bw], bl1 = Blo[bw + 4 * B_STRIDE];
#pragma unroll
                for (int rs = 0; rs < 2; rs++) {
                    mma_bf16(c[rs][nf], ah[rs], bh0, bh1);
                    mma_bf16(c[rs][nf], ah[rs], bl0, bl1);
                    mma_bf16(c[rs][nf], al[rs], bh0, bh1);
                }
            }
        }
    }

#pragma unroll
    for (int rs = 0; rs < 2; rs++) {
#pragma unroll
        for (int hh = 0; hh < 2; hh++) {
            int row = wr * 32 + rs * 16 + (lane >> 2) + hh * 8;
            int node = nbase + row;
            float ss[4] = {0.f, 0.f, 0.f, 0.f};
            float dd[4] = {0.f, 0.f, 0.f, 0.f};
#pragma unroll
            for (int nf = 0; nf < 8; nf++) {
                float v0 = c[rs][nf][hh * 2];
                float v1 = c[rs][nf][hh * 2 + 1];
                int col = wc * 64 + nf * 8 + (lane & 3) * 2;
                if (node < NN)
                    *(float2*)&g_H1[node * 128 + col] = make_float2(v0, v1);
                int hp = nf >> 1;
                int wcol = (nf & 1) * 8 + (lane & 3) * 2;
                int hb = (wc * 4 + hp) * 16 + wcol;
                ss[hp] += v0 * __ldg(&as[hb]) + v1 * __ldg(&as[hb + 1]);
                dd[hp] += v0 * __ldg(&ad[hb]) + v1 * __ldg(&ad[hb + 1]);
            }
#pragma unroll
            for (int hp = 0; hp < 4; hp++) {
                ss[hp] += __shfl_xor_sync(0xffffffffu, ss[hp], 1);
                ss[hp] += __shfl_xor_sync(0xffffffffu, ss[hp], 2);
                dd[hp] += __shfl_xor_sync(0xffffffffu, dd[hp], 1);
                dd[hp] += __shfl_xor_sync(0xffffffffu, dd[hp], 2);
            }
            if ((lane & 3) == 0 && node < NN) {
#pragma unroll
                for (int hp = 0; hp < 4; hp++) {
                    g_asrc1[node * 8 + wc * 4 + hp] = ss[hp] * LOG2E;
                    g_adst1[node * 8 + wc * 4 + hp] = dd[hp] * LOG2E;
                }
            }
        }
    }
}

// ---------------- layer-1 aggregation: warp per dst, unroll 8, int4 csr --------
__global__ void __launch_bounds__(256, 5)
agg1_kernel(const float* __restrict__ b1, int base, int cnt) {
    int w = base + ((blockIdx.x * blockDim.x + threadIdx.x) >> 5);
    int l = threadIdx.x & 31;
    if (w >= base + cnt || w >= NN) return;
    int d = w;
    int start = d << 7;
    int end = start + __ldg(&g_deg[d]);
    int hl = l >> 2;

    float adh = __ldg(&g_adst1[d * 8 + hl]);
    float wself = ex2(lrelu(__ldg(&g_asrc1[d * 8 + hl]) + adh));

    float den0 = wself, den1 = 0.f, den2 = 0.f, den3 = 0.f;
    float4 acc0, acc1, acc2, acc3;
    {
        float4 v = __ldg(((const float4*)g_H1) + d * 32 + l);
        acc0.x = wself * v.x; acc0.y = wself * v.y;
        acc0.z = wself * v.z; acc0.w = wself * v.w;
        acc1 = make_float4(0.f, 0.f, 0.f, 0.f);
        acc2 = make_float4(0.f, 0.f, 0.f, 0.f);
        acc3 = make_float4(0.f, 0.f, 0.f, 0.f);
    }

    int e = start;
    for (; e + 7 < end; e += 8) {
        int4 ca = __ldg((const int4*)(g_csr + e));
        int4 cb = __ldg((const int4*)(g_csr + e + 4));
        float w0 = ex2(lrelu(__ldg(&g_asrc1[ca.x * 8 + hl]) + adh));
        float w1 = ex2(lrelu(__ldg(&g_asrc1[ca.y * 8 + hl]) + adh));
        float w2 = ex2(lrelu(__ldg(&g_asrc1[ca.z * 8 + hl]) + adh));
        float w3 = ex2(lrelu(__ldg(&g_asrc1[ca.w * 8 + hl]) + adh));
        float w4 = ex2(lrelu(__ldg(&g_asrc1[cb.x * 8 + hl]) + adh));
        float w5 = ex2(lrelu(__ldg(&g_asrc1[cb.y * 8 + hl]) + adh));
        float w6 = ex2(lrelu(__ldg(&g_asrc1[cb.z * 8 + hl]) + adh));
        float w7 = ex2(lrelu(__ldg(&g_asrc1[cb.w * 8 + hl]) + adh));
        float4 v0 = __ldg(((const float4*)g_H1) + ca.x * 32 + l);
        float4 v1 = __ldg(((const float4*)g_H1) + ca.y * 32 + l);
        float4 v2 = __ldg(((const float4*)g_H1) + ca.z * 32 + l);
        float4 v3 = __ldg(((const float4*)g_H1) + ca.w * 32 + l);
        float4 v4 = __ldg(((const float4*)g_H1) + cb.x * 32 + l);
        float4 v5 = __ldg(((const float4*)g_H1) + cb.y * 32 + l);
        float4 v6 = __ldg(((const float4*)g_H1) + cb.z * 32 + l);
        float4 v7 = __ldg(((const float4*)g_H1) + cb.w * 32 + l);
        den0 += w0 + w4; den1 += w1 + w5; den2 += w2 + w6; den3 += w3 + w7;
        acc0.x += w0 * v0.x + w4 * v4.x; acc0.y += w0 * v0.y + w4 * v4.y;
        acc0.z += w0 * v0.z + w4 * v4.z; acc0.w += w0 * v0.w + w4 * v4.w;
        acc1.x += w1 * v1.x + w5 * v5.x; acc1.y += w1 * v1.y + w5 * v5.y;
        acc1.z += w1 * v1.z + w5 * v5.z; acc1.w += w1 * v1.w + w5 * v5.w;
        acc2.x += w2 * v2.x + w6 * v6.x; acc2.y += w2 * v2.y + w6 * v6.y;
        acc2.z += w2 * v2.z + w6 * v6.z; acc2.w += w2 * v2.w + w6 * v6.w;
        acc3.x += w3 * v3.x + w7 * v7.x; acc3.y += w3 * v3.y + w7 * v7.y;
        acc3.z += w3 * v3.z + w7 * v7.z; acc3.w += w3 * v3.w + w7 * v7.w;
    }
    for (; e < end; e++) {
        int s0 = __ldg(&g_csr[e]);
        float w0 = ex2(lrelu(__ldg(&g_asrc1[s0 * 8 + hl]) + adh));
        float4 v0 = __ldg(((const float4*)g_H1) + s0 * 32 + l);
        den0 += w0;
        acc0.x += w0 * v0.x; acc0.y += w0 * v0.y;
        acc0.z += w0 * v0.z; acc0.w += w0 * v0.w;
    }

    float inv = 1.f / ((den0 + den1) + (den2 + den3));
    float4 bb = ((const float4*)b1)[l];
    float4 r;
    r.x = ((acc0.x + acc1.x) + (acc2.x + acc3.x)) * inv + bb.x;
    r.y = ((acc0.y + acc1.y) + (acc2.y + acc3.y)) * inv + bb.y;
    r.z = ((acc0.z + acc1.z) + (acc2.z + acc3.z)) * inv + bb.z;
    r.w = ((acc0.w + acc1.w) + (acc2.w + acc3.w)) * inv + bb.w;
    r.x = r.x > 0.f ? r.x : __expf(r.x) - 1.f;
    r.y = r.y > 0.f ? r.y : __expf(r.y) - 1.f;
    r.z = r.z > 0.f ? r.z : __expf(r.z) - 1.f;
    r.w = r.w > 0.f ? r.w : __expf(r.w) - 1.f;
    ((float4*)g_out1)[d * 32 + l] = r;
}

// ---------------- GEMM2 via mma.sync bf16 split + fused attn2 (tile offset) ----
#define SM2_ALO (128 * A2_STRIDE)
#define SM2_BHI (2 * 128 * A2_STRIDE)
#define SM2_BLO (2 * 128 * A2_STRIDE + 64 * B2_STRIDE)
#define SM2_WORDS (2 * 128 * A2_STRIDE + 2 * 64 * B2_STRIDE)

__global__ void __launch_bounds__(256, 2)
gemm2_mma_kernel(const float* __restrict__ as2, const float* __restrict__ ad2,
                 int tile0) {
    extern __shared__ uint32_t sm[];
    uint32_t* Ahi = sm;
    uint32_t* Alo = sm + SM2_ALO;
    uint32_t* Bhi = sm + SM2_BHI;
    uint32_t* Blo = sm + SM2_BLO;

    int t = threadIdx.x, wid = t >> 5, lane = t & 31;
    int nbase = (tile0 + blockIdx.x) * 128;

#pragma unroll
    for (int i = 0; i < 16; i++) {
        int idx = t + 256 * i;
        int r = idx >> 5, c4 = idx & 31;
        int node = nbase + r;
        float4 v = make_float4(0.f, 0.f, 0.f, 0.f);
        if (node < NN) v = ((const float4*)g_out1)[node * 32 + c4];
        uint32_t h0 = pack_bf2(v.x, v.y), h1 = pack_bf2(v.z, v.w);
        __nv_bfloat162 hh0 = *(__nv_bfloat162*)&h0;
        __nv_bfloat162 hh1 = *(__nv_bfloat162*)&h1;
        uint32_t l0 = pack_bf2(v.x - __bfloat162float(hh0.x), v.y - __bfloat162float(hh0.y));
        uint32_t l1 = pack_bf2(v.z - __bfloat162float(hh1.x), v.w - __bfloat162float(hh1.y));
        int w = r * A2_STRIDE + c4 * 2;
        Ahi[w] = h0; Ahi[w + 1] = h1;
        Alo[w] = l0; Alo[w + 1] = l1;
    }
    // copy precomputed W2 tiles (int4): 704 int4 per buffer
#pragma unroll
    for (int i = 0; i < 3; i++) {
        int idx = t + 256 * i;
        if (idx < 704) {
            ((int4*)Bhi)[idx] = __ldg((const int4*)g_W2h + idx);
            ((int4*)Blo)[idx] = __ldg((const int4*)g_W2l + idx);
        }
    }
    __syncthreads();

    float c[5][4];
#pragma unroll
    for (int nf = 0; nf < 5; nf++)
#pragma unroll
        for (int q = 0; q < 4; q++) c[nf][q] = 0.f;

#pragma unroll
    for (int kk = 0; kk < 8; kk++) {
        int base = (wid * 16 + (lane >> 2)) * A2_STRIDE + kk * 8 + (lane & 3);
        uint32_t ah[4], al[4];
        ah[0] = Ahi[base];
        ah[1] = Ahi[base + 8 * A2_STRIDE];
        ah[2] = Ahi[base + 4];
        ah[3] = Ahi[base + 8 * A2_STRIDE + 4];
        al[0] = Alo[base];
        al[1] = Alo[base + 8 * A2_STRIDE];
        al[2] = Alo[base + 4];
        al[3] = Alo[base + 8 * A2_STRIDE + 4];
#pragma unroll
        for (int nf = 0; nf < 5; nf++) {
            int j = nf * 8 + (lane >> 2);
            int bw = (kk * 8 + (lane & 3)) * B2_STRIDE + j;
            uint32_t bh0 = Bhi[bw], bh1 = Bhi[bw + 4 * B2_STRIDE];
            uint32_t bl0 = Blo[bw], bl1 = Blo[bw + 4 * B2_STRIDE];
            mma_bf16(c[nf], ah, bh0, bh1);
            mma_bf16(c[nf], ah, bl0, bl1);
            mma_bf16(c[nf], al, bh0, bh1);
        }
    }

#pragma unroll
    for (int hh = 0; hh < 2; hh++) {
        int row = wid * 16 + (lane >> 2) + hh * 8;
        int node = nbase + row;
        float ps = 0.f, pd = 0.f;
#pragma unroll
        for (int nf = 0; nf < 5; nf++) {
            float v0 = c[nf][hh * 2];
            float v1 = c[nf][hh * 2 + 1];
            int col = nf * 8 + (lane & 3) * 2;
            if (node < NN)
                *(float2*)&g_H2[node * NCLS + col] = make_float2(v0, v1);
            ps += v0 * __ldg(&as2[col]) + v1 * __ldg(&as2[col + 1]);
            pd += v0 * __ldg(&ad2[col]) + v1 * __ldg(&ad2[col + 1]);
        }
        ps += __shfl_xor_sync(0xffffffffu, ps, 1);
        ps += __shfl_xor_sync(0xffffffffu, ps, 2);
        pd += __shfl_xor_sync(0xffffffffu, pd, 1);
        pd += __shfl_xor_sync(0xffffffffu, pd, 2);
        if ((lane & 3) == 0 && node < NN) {
            g_asrc2[node] = ps * LOG2E;
            g_adst2[node] = pd * LOG2E;
        }
    }
}

// ---------------- layer-2 aggregation: warp per dst, unroll 8; resets g_deg -----
__global__ void __launch_bounds__(256, 5)
agg2_kernel(const float* __restrict__ b2, float* __restrict__ out) {
    int w = (blockIdx.x * blockDim.x + threadIdx.x) >> 5;
    int l = threadIdx.x & 31;
    if (w >= NN) return;
    int d = w;
    int start = d << 7;
    int deg = __ldg(&g_deg[d]);
    int end = start + deg;

    float adst = __ldg(&g_adst2[d]);
    float wself = ex2(lrelu(__ldg(&g_asrc2[d]) + adst));

    float den0 = wself, den1 = 0.f, den2 = 0.f, den3 = 0.f;
    float accA0 = wself * __ldg(&g_H2[d * NCLS + l]);
    float accA1 = 0.f, accA2 = 0.f, accA3 = 0.f;
    float accB0 = (l < 8) ? wself * __ldg(&g_H2[d * NCLS + 32 + l]) : 0.f;
    float accB1 = 0.f, accB2 = 0.f, accB3 = 0.f;

    int e = start;
    for (; e + 7 < end; e += 8) {
        int4 ca = __ldg((const int4*)(g_csr + e));
        int4 cb = __ldg((const int4*)(g_csr + e + 4));
        float w0 = ex2(lrelu(__ldg(&g_asrc2[ca.x]) + adst));
        float w1 = ex2(lrelu(__ldg(&g_asrc2[ca.y]) + adst));
        float w2 = ex2(lrelu(__ldg(&g_asrc2[ca.z]) + adst));
        float w3 = ex2(lrelu(__ldg(&g_asrc2[ca.w]) + adst));
        float w4 = ex2(lrelu(__ldg(&g_asrc2[cb.x]) + adst));
        float w5 = ex2(lrelu(__ldg(&g_asrc2[cb.y]) + adst));
        float w6 = ex2(lrelu(__ldg(&g_asrc2[cb.z]) + adst));
        float w7 = ex2(lrelu(__ldg(&g_asrc2[cb.w]) + adst));
        den0 += w0 + w4; den1 += w1 + w5; den2 += w2 + w6; den3 += w3 + w7;
        accA0 += w0 * __ldg(&g_H2[ca.x * NCLS + l]) + w4 * __ldg(&g_H2[cb.x * NCLS + l]);
        accA1 += w1 * __ldg(&g_H2[ca.y * NCLS + l]) + w5 * __ldg(&g_H2[cb.y * NCLS + l]);
        accA2 += w2 * __ldg(&g_H2[ca.z * NCLS + l]) + w6 * __ldg(&g_H2[cb.z * NCLS + l]);
        accA3 += w3 * __ldg(&g_H2[ca.w * NCLS + l]) + w7 * __ldg(&g_H2[cb.w * NCLS + l]);
        if (l < 8) {
            accB0 += w0 * __ldg(&g_H2[ca.x * NCLS + 32 + l]) + w4 * __ldg(&g_H2[cb.x * NCLS + 32 + l]);
            accB1 += w1 * __ldg(&g_H2[ca.y * NCLS + 32 + l]) + w5 * __ldg(&g_H2[cb.y * NCLS + 32 + l]);
            accB2 += w2 * __ldg(&g_H2[ca.z * NCLS + 32 + l]) + w6 * __ldg(&g_H2[cb.z * NCLS + 32 + l]);
            accB3 += w3 * __ldg(&g_H2[ca.w * NCLS + 32 + l]) + w7 * __ldg(&g_H2[cb.w * NCLS + 32 + l]);
        }
    }
    for (; e < end; e++) {
        int s0 = __ldg(&g_csr[e]);
        float w0 = ex2(lrelu(__ldg(&g_asrc2[s0]) + adst));
        den0 += w0;
        accA0 += w0 * __ldg(&g_H2[s0 * NCLS + l]);
        if (l < 8) accB0 += w0 * __ldg(&g_H2[s0 * NCLS + 32 + l]);
    }

    float inv = 1.f / ((den0 + den1) + (den2 + den3));
    out[d * NCLS + l] = ((accA0 + accA1) + (accA2 + accA3)) * inv + b2[l];
    if (l < 8) out[d * NCLS + 32 + l] = ((accB0 + accB1) + (accB2 + accB3)) * inv + b2[32 + l];
    if (l == 0) g_deg[d] = 0;   // restore invariant for next replay
}

// ---------------- launch: 4-chunk agg1/gemm2 software pipeline ----------------
static cudaStream_t g_s2 = nullptr;
static cudaEvent_t g_evFork = nullptr, g_evJoin = nullptr, g_evG = nullptr;
static cudaEvent_t g_evC[NCHUNK] = {nullptr, nullptr, nullptr, nullptr};

extern "C" void kernel_launch(void* const* d_in, const int* in_sizes, int n_in,
                              void* d_out, int out_size) {
    const float* x   = (const float*)d_in[0];
    const int*   ei  = (const int*)d_in[1];     // int32 (JAX x64 disabled)
    const float* W1  = (const float*)d_in[2];
    const float* as1 = (const float*)d_in[3];
    const float* ad1 = (const float*)d_in[4];
    const float* b1  = (const float*)d_in[5];
    const float* W2  = (const float*)d_in[6];
    const float* as2 = (const float*)d_in[7];
    const float* ad2 = (const float*)d_in[8];
    const float* b2  = (const float*)d_in[9];
    float* out = (float*)d_out;

    if (g_s2 == nullptr) {
        cudaStreamCreateWithFlags(&g_s2, cudaStreamNonBlocking);
        cudaEventCreateWithFlags(&g_evFork, cudaEventDisableTiming);
        cudaEventCreateWithFlags(&g_evJoin, cudaEventDisableTiming);
        cudaEventCreateWithFlags(&g_evG, cudaEventDisableTiming);
        for (int i = 0; i < NCHUNK; i++)
            cudaEventCreateWithFlags(&g_evC[i], cudaEventDisableTiming);
        cudaFuncSetAttribute(gemm1_mma_kernel,
                             cudaFuncAttributeMaxDynamicSharedMemorySize, SM_WORDS * 4);
        cudaFuncSetAttribute(gemm2_mma_kernel,
                             cudaFuncAttributeMaxDynamicSharedMemorySize, SM2_WORDS * 4);
    }

    // fork: single-pass padded-CSR fill on side stream (g_deg zeroed by agg2)
    cudaEventRecord(g_evFork, 0);
    cudaStreamWaitEvent(g_s2, g_evFork, 0);
    fill_kernel<<<(EE / 4 + 255) / 256, 256, 0, g_s2>>>(ei);
    cudaEventRecord(g_evJoin, g_s2);

    // main stream: weight prep, then tensor-core GEMM1 with fused attn1
    prep_kernel<<<(16384 + 5120 + 255) / 256, 256>>>(W1, W2);
    gemm1_mma_kernel<<<NTILES, 256, SM_WORDS * 4>>>(x, as1, ad1);

    // join; then 4-chunk pipeline: agg1 chunks back-to-back on main,
    // gemm2 chunks released on side stream as each agg1 chunk completes
    cudaStreamWaitEvent(0, g_evJoin, 0);
    for (int i = 0; i < NCHUNK; i++) {
        int tile0 = CH_TILE0(i), tiles = CH_TILES(i);
        int nb = tile0 * 128;
        int ncnt = (i == NCHUNK - 1) ? (NN - nb) : tiles * 128;
        agg1_kernel<<<(ncnt * 32 + 255) / 256, 256>>>(b1, nb, ncnt);
        cudaEventRecord(g_evC[i], 0);
        cudaStreamWaitEvent(g_s2, g_evC[i], 0);
        gemm2_mma_kernel<<<tiles, 256, SM2_WORDS * 4, g_s2>>>(as2, ad2, tile0);
    }
    cudaEventRecord(g_evG, g_s2);

    cudaStreamWaitEvent(0, g_evG, 0);
    agg2_kernel<<<(NN * 32 + 255) / 256, 256>>>(b2, out);
}